// round 10
// baseline (speedup 1.0000x reference)
#include <cuda_runtime.h>
#include <math.h>

// ToneStack: 3 cascaded low-shelf biquads over x:[64, 480000] fp32.
// TWO kernels: slim setup + one streaming fused kernel.
// Fused kernel (block = 5 warps x 30 chunks of 128 = 150 chunks = 1/25 row):
//   sweep1: warp-transpose staged W-reduction -> per-chunk zero-state finals
//   scan  : in-block subgroup tree + decoupled lookback (<=24 same-row
//           predecessors, powers of Tb = T^150) -> per-chunk entry states
//   sweep2: warp-transpose staged serial filter, coalesced y store.
// DRAM traffic = 2 reads of x + 1 write of y (369 MB), no state round trips.

#define TLEN    480000
#define NROW    64
#define CHUNK   128
#define WCH     30               // chunks per warp
#define NWPB    5                // warps per block
#define BCH     (NWPB * WCH)     // 150 chunks per block
#define BROW    25               // blocks per row (150*128*25 = 480000)
#define GRID    (NROW * BROW)    // 1600
#define NLOOK   25
#define THREADS 160

__device__ float g_coef[15];         // per stage: b0, c1, c2, -a1, -a2
__device__ float g_T[36];            // A^128
__device__ float g_T5[36];           // T^5
__device__ float g_T30[36];          // T^30
__device__ float g_Tbp[NLOOK * 36];  // (T^150)^p, p = 0..24
__device__ float g_W6[6][CHUNK];     // transposed reduction weights
__device__ float g_F[GRID * 6];      // block aggregates
__device__ int   g_flag[GRID];       // publication flags

// ---------------------------------------------------------------- setup ----

__device__ void shelf_coefs(double fc, double gdb, double Q, double* out) {
    const double PI = 3.14159265358979323846;
    double A  = pow(10.0, gdb / 40.0);
    double w0 = 2.0 * PI * fc / 48000.0;
    double al = sin(w0) / (2.0 * Q);
    double cw = cos(w0);
    double sq = sqrt(A);
    double b0 = A * ((A + 1.0) - (A - 1.0) * cw + 2.0 * sq * al);
    double b1 = 2.0 * A * ((A - 1.0) - (A + 1.0) * cw);
    double b2 = A * ((A + 1.0) - (A - 1.0) * cw - 2.0 * sq * al);
    double a0 = (A + 1.0) + (A - 1.0) * cw + 2.0 * sq * al;
    double a1 = -2.0 * ((A - 1.0) + (A + 1.0) * cw);
    double a2 = (A + 1.0) + (A - 1.0) * cw - 2.0 * sq * al;
    b0 /= a0; b1 /= a0; b2 /= a0; a1 /= a0; a2 /= a0;
    out[0] = b0;
    out[1] = b1 - a1 * b0;   // c1
    out[2] = b2 - a2 * b0;   // c2
    out[3] = -a1;
    out[4] = -a2;
}

#define MATMUL(D, A_, B_)                                                     \
    do {                                                                      \
        if (tid < 36) {                                                       \
            int r_ = tid / 6, c_ = tid % 6;                                   \
            float acc_ = 0.f;                                                 \
            for (int k_ = 0; k_ < 6; k_++)                                    \
                acc_ += (A_)[r_ * 6 + k_] * (B_)[k_ * 6 + c_];                \
            (D)[tid] = acc_;                                                  \
        }                                                                     \
        __syncthreads();                                                      \
    } while (0)

__global__ void setup_kernel(const float* lg, const float* mg, const float* mfc,
                             const float* mq, const float* hg) {
    __shared__ double scoef[15];
    __shared__ double db[6];
    __shared__ float sP[7][36];   // A^(2^k), k = 0..6
    __shared__ float M0[36], M1[36], M2[36], M3[36], M4[36];
    int tid = threadIdx.x;

    for (int i = tid; i < GRID; i += 256) g_flag[i] = 0;

    if (tid == 0) {
        double c[5];
        shelf_coefs(120.0, (double)*lg, (double)0.707f, c);
        for (int i = 0; i < 5; i++) { scoef[i] = c[i];      g_coef[i]      = (float)c[i]; }
        shelf_coefs((double)*mfc, (double)*mg, (double)*mq, c);
        for (int i = 0; i < 5; i++) { scoef[5 + i] = c[i];  g_coef[5 + i]  = (float)c[i]; }
        shelf_coefs(4000.0, (double)*hg, (double)0.707f, c);
        for (int i = 0; i < 5; i++) { scoef[10 + i] = c[i]; g_coef[10 + i] = (float)c[i]; }
    }
    __syncthreads();

    // one-step 6x6 matrix A (column j = step(e_j, x=0)) and input vector b
    if (tid < 6) {
        double z[6] = {0, 0, 0, 0, 0, 0};
        z[tid] = 1.0;
        double u = 0.0;
        double ns[6];
        for (int st = 0; st < 3; st++) {
            double b0  = scoef[st * 5 + 0], c1 = scoef[st * 5 + 1], c2 = scoef[st * 5 + 2];
            double na1 = scoef[st * 5 + 3], na2 = scoef[st * 5 + 4];
            double z1 = z[2 * st], z2 = z[2 * st + 1];
            double y = b0 * u + z1;
            ns[2 * st]     = c1 * u + na1 * z1 + z2;
            ns[2 * st + 1] = c2 * u + na2 * z1;
            u = y;
        }
        for (int i = 0; i < 6; i++) M0[i * 6 + tid] = (float)ns[i];
    }
    if (tid == 0) {
        double y0 = scoef[0];
        double y1 = scoef[5] * y0;
        db[0] = scoef[1];  db[1] = scoef[2];
        db[2] = scoef[6] * y0;   db[3] = scoef[7] * y0;
        db[4] = scoef[11] * y1;  db[5] = scoef[12] * y1;
    }
    __syncthreads();

    // A powers for W; T = A^128
    if (tid < 36) sP[0][tid] = M0[tid];
    __syncthreads();
    MATMUL(M1, M0, M0);  if (tid < 36) sP[1][tid] = M1[tid];   // A^2
    MATMUL(M0, M1, M1);  if (tid < 36) sP[2][tid] = M0[tid];   // A^4
    MATMUL(M1, M0, M0);  if (tid < 36) sP[3][tid] = M1[tid];   // A^8
    MATMUL(M0, M1, M1);  if (tid < 36) sP[4][tid] = M0[tid];   // A^16
    MATMUL(M1, M0, M0);  if (tid < 36) sP[5][tid] = M1[tid];   // A^32
    MATMUL(M0, M1, M1);  if (tid < 36) sP[6][tid] = M0[tid];   // A^64
    MATMUL(M1, M0, M0);                                        // A^128 = T
    if (tid < 36) g_T[tid] = M1[tid];
    __syncthreads();

    // T5, T30, Tb = T^150
    MATMUL(M0, M1, M1);        // T^2
    MATMUL(M2, M0, M0);        // T^4
    MATMUL(M3, M2, M1);        // T^5
    if (tid < 36) g_T5[tid] = M3[tid];
    __syncthreads();
    MATMUL(M0, M3, M3);        // T^10
    MATMUL(M2, M0, M0);        // T^20
    MATMUL(M4, M2, M0);        // T^30
    if (tid < 36) g_T30[tid] = M4[tid];
    __syncthreads();
    MATMUL(M0, M4, M4);        // T^60
    MATMUL(M2, M0, M0);        // T^120
    MATMUL(M3, M2, M4);        // T^150 = Tb (keep in M3)

    // Tbp[p] = Tb^p, p = 0..24
    if (tid < 36) {
        float idv = (tid % 7 == 0) ? 1.f : 0.f;
        M1[tid] = idv;
        g_Tbp[tid] = idv;
    }
    __syncthreads();
    for (int p = 1; p < NLOOK; p++) {
        MATMUL(M2, M1, M3);
        if (tid < 36) { g_Tbp[p * 36 + tid] = M2[tid]; M1[tid] = M2[tid]; }
        __syncthreads();
    }

    // W[n] = A^(127-n) b, one thread per n (powers commute)
    if (tid < CHUNK) {
        int e = CHUNK - 1 - tid;
        float v[6];
#pragma unroll
        for (int j = 0; j < 6; j++) v[j] = (float)db[j];
#pragma unroll
        for (int k = 0; k < 7; k++) {
            if ((e >> k) & 1) {
                float nv[6];
#pragma unroll
                for (int j = 0; j < 6; j++) {
                    float acc = 0.f;
#pragma unroll
                    for (int kk = 0; kk < 6; kk++)
                        acc = fmaf(sP[k][j * 6 + kk], v[kk], acc);
                    nv[j] = acc;
                }
#pragma unroll
                for (int j = 0; j < 6; j++) v[j] = nv[j];
            }
        }
#pragma unroll
        for (int j = 0; j < 6; j++) g_W6[j][tid] = v[j];
    }
}

// ---------------------------------------------------------------- fused ----

__device__ __forceinline__ float step_all(float u, float z[6], const float k[15]) {
    float y0 = fmaf(k[0], u, z[0]);
    float t0 = fmaf(k[3], z[0], z[1]);
    z[1] = fmaf(k[2], u, k[4] * z[0]);
    z[0] = fmaf(k[1], u, t0);
    float y1 = fmaf(k[5], y0, z[2]);
    float t1 = fmaf(k[8], z[2], z[3]);
    z[3] = fmaf(k[7], y0, k[9] * z[2]);
    z[2] = fmaf(k[6], y0, t1);
    float y2 = fmaf(k[10], y1, z[4]);
    float t2 = fmaf(k[13], z[4], z[5]);
    z[5] = fmaf(k[12], y1, k[14] * z[4]);
    z[4] = fmaf(k[11], y1, t2);
    return y2;
}

// affine: s <- T*s + fv  (T, fv in shared memory; broadcast reads)
__device__ __forceinline__ void affine_sm(float s[6], const float* fv,
                                          const float* T) {
    float ns[6];
#pragma unroll
    for (int j = 0; j < 6; j++) {
        float acc = fv[j];
#pragma unroll
        for (int kk = 0; kk < 6; kk++) acc = fmaf(T[j * 6 + kk], s[kk], acc);
        ns[j] = acc;
    }
#pragma unroll
    for (int j = 0; j < 6; j++) s[j] = ns[j];
}

__global__ __launch_bounds__(THREADS) void fused_kernel(const float* __restrict__ x,
                                                        float* __restrict__ y) {
    __shared__ float sbuf[NWPB][WCH][36];     // per-warp transpose tiles
    __shared__ float sw6[6][CHUNK];
    __shared__ float sk[15];
    __shared__ float sT[36], sT5[36], sT30[36];
    __shared__ float sfin[BCH][6];
    __shared__ float ssga[NWPB][6][6];        // subgroup aggregates
    __shared__ float sWA[NWPB][6];            // warp aggregates
    __shared__ float sWE[NWPB][6];            // warp entry states
    __shared__ float sSE[NWPB][6][6];         // subgroup entry states
    __shared__ float sS[6];                   // block entry state

    int tid = threadIdx.x, ws = tid >> 5, lane = tid & 31;
    int bid = blockIdx.x;
    int r = bid / BROW, jb = bid % BROW;
    const float4* xw4 = (const float4*)(x + (size_t)r * TLEN + (size_t)jb * BCH * CHUNK)
                        + (size_t)ws * WCH * (CHUNK / 4);
    float4* yw4 = (float4*)(y + (size_t)r * TLEN + (size_t)jb * BCH * CHUNK)
                  + (size_t)ws * WCH * (CHUNK / 4);

    for (int i = tid; i < 6 * CHUNK / 4; i += THREADS)
        ((float4*)sw6)[i] = ((const float4*)g_W6)[i];
    if (tid < 36) { sT[tid] = g_T[tid]; sT5[tid] = g_T5[tid]; sT30[tid] = g_T30[tid]; }
    if (tid < 15) sk[tid] = g_coef[tid];
    __syncthreads();

    float (*buf)[36] = sbuf[ws];
    // tile staging: 240 float4 per (warp, tile); i -> chunk i>>3, slot i&7.

    // ---------------- sweep 1: W-reduction -> finals ----------------
    float f0 = 0.f, f1 = 0.f, f2 = 0.f, f3 = 0.f, f4 = 0.f, f5 = 0.f;
    float4 pre[8];
#pragma unroll
    for (int kq = 0; kq < 8; kq++) {
        int i = lane + kq * 32;
        if (i < 240) pre[kq] = xw4[(i >> 3) * 32 + (i & 7)];
    }
#pragma unroll
    for (int t = 0; t < 4; t++) {
#pragma unroll
        for (int kq = 0; kq < 8; kq++) {
            int i = lane + kq * 32;
            if (i < 240) *(float4*)&buf[i >> 3][(i & 7) * 4] = pre[kq];
        }
        __syncwarp();
        if (t < 3) {
#pragma unroll
            for (int kq = 0; kq < 8; kq++) {
                int i = lane + kq * 32;
                if (i < 240) pre[kq] = xw4[(i >> 3) * 32 + (t + 1) * 8 + (i & 7)];
            }
        }
        if (lane < WCH) {
            const float4* my = (const float4*)buf[lane];
#pragma unroll
            for (int q = 0; q < 8; q++) {
                float4 v = my[q];
                int n = t * 32 + q * 4;
                float4 w0 = *(const float4*)&sw6[0][n];
                float4 w1 = *(const float4*)&sw6[1][n];
                float4 w2 = *(const float4*)&sw6[2][n];
                float4 w3 = *(const float4*)&sw6[3][n];
                float4 w4 = *(const float4*)&sw6[4][n];
                float4 w5 = *(const float4*)&sw6[5][n];
                f0 = fmaf(v.w, w0.w, fmaf(v.z, w0.z, fmaf(v.y, w0.y, fmaf(v.x, w0.x, f0))));
                f1 = fmaf(v.w, w1.w, fmaf(v.z, w1.z, fmaf(v.y, w1.y, fmaf(v.x, w1.x, f1))));
                f2 = fmaf(v.w, w2.w, fmaf(v.z, w2.z, fmaf(v.y, w2.y, fmaf(v.x, w2.x, f2))));
                f3 = fmaf(v.w, w3.w, fmaf(v.z, w3.z, fmaf(v.y, w3.y, fmaf(v.x, w3.x, f3))));
                f4 = fmaf(v.w, w4.w, fmaf(v.z, w4.z, fmaf(v.y, w4.y, fmaf(v.x, w4.x, f4))));
                f5 = fmaf(v.w, w5.w, fmaf(v.z, w5.z, fmaf(v.y, w5.y, fmaf(v.x, w5.x, f5))));
            }
        }
        __syncwarp();
    }
    if (lane < WCH) {
        float* f = sfin[ws * WCH + lane];
        f[0] = f0; f[1] = f1; f[2] = f2; f[3] = f3; f[4] = f4; f[5] = f5;
    }
    __syncwarp();

    // ---------------- in-block scan + lookback ----------------
    // subgroup aggregates (6 subgroups of 5 chunks per warp)
    if (lane < 6) {
        float s[6] = {0, 0, 0, 0, 0, 0};
        for (int i = 0; i < 5; i++)
            affine_sm(s, sfin[ws * WCH + lane * 5 + i], sT);
#pragma unroll
        for (int z = 0; z < 6; z++) ssga[ws][lane][z] = s[z];
    }
    __syncwarp();
    if (lane == 0) {
        float s[6] = {0, 0, 0, 0, 0, 0};
        for (int k = 0; k < 6; k++) affine_sm(s, ssga[ws][k], sT5);
#pragma unroll
        for (int z = 0; z < 6; z++) sWA[ws][z] = s[z];
    }
    __syncthreads();

    if (tid == 0) {   // block aggregate; publish FIRST (forward progress)
        float s[6] = {0, 0, 0, 0, 0, 0};
        for (int w = 0; w < NWPB; w++) affine_sm(s, sWA[w], sT30);
#pragma unroll
        for (int z = 0; z < 6; z++) __stcg(&g_F[bid * 6 + z], s[z]);
        __threadfence();
        atomicExch(&g_flag[bid], 1);
    }
    if (ws == 0) {    // lookback: lane p handles predecessor at distance p
        float acc[6] = {0, 0, 0, 0, 0, 0};
        if (lane < jb) {
            int q = bid - 1 - lane;
            while (atomicAdd(&g_flag[q], 0) == 0) __nanosleep(40);
            __threadfence();
            float Fv[6];
#pragma unroll
            for (int z = 0; z < 6; z++) Fv[z] = __ldcg(&g_F[q * 6 + z]);
            const float* P = &g_Tbp[lane * 36];
#pragma unroll
            for (int z = 0; z < 6; z++) {
                float a = 0.f;
#pragma unroll
                for (int kk = 0; kk < 6; kk++) a = fmaf(P[z * 6 + kk], Fv[kk], a);
                acc[z] = a;
            }
        }
#pragma unroll
        for (int o = 16; o > 0; o >>= 1)
#pragma unroll
            for (int z = 0; z < 6; z++)
                acc[z] += __shfl_down_sync(0xFFFFFFFFu, acc[z], o);
        if (lane == 0) {
#pragma unroll
            for (int z = 0; z < 6; z++) sS[z] = acc[z];
        }
    }
    __syncthreads();

    if (tid == 0) {   // warp entry states
        float s[6];
#pragma unroll
        for (int z = 0; z < 6; z++) s[z] = sS[z];
        for (int w = 0; w < NWPB; w++) {
#pragma unroll
            for (int z = 0; z < 6; z++) sWE[w][z] = s[z];
            affine_sm(s, sWA[w], sT30);
        }
    }
    __syncthreads();
    if (lane == 0) {  // subgroup entry states within warp
        float s[6];
#pragma unroll
        for (int z = 0; z < 6; z++) s[z] = sWE[ws][z];
        for (int k = 0; k < 6; k++) {
#pragma unroll
            for (int z = 0; z < 6; z++) sSE[ws][k][z] = s[z];
            affine_sm(s, ssga[ws][k], sT5);
        }
    }
    __syncwarp();

    // per-lane chunk entry state
    float zst[6] = {0, 0, 0, 0, 0, 0};
    if (lane < WCH) {
        int kg = lane / 5, o = lane % 5;
#pragma unroll
        for (int z = 0; z < 6; z++) zst[z] = sSE[ws][kg][z];
        for (int i = 0; i < o; i++)
            affine_sm(zst, sfin[ws * WCH + kg * 5 + i], sT);
    }

    // ---------------- sweep 2: serial filter, write y ----------------
    float kc[15];
#pragma unroll
    for (int i = 0; i < 15; i++) kc[i] = sk[i];
#pragma unroll
    for (int kq = 0; kq < 8; kq++) {
        int i = lane + kq * 32;
        if (i < 240) pre[kq] = xw4[(i >> 3) * 32 + (i & 7)];
    }
#pragma unroll
    for (int t = 0; t < 4; t++) {
#pragma unroll
        for (int kq = 0; kq < 8; kq++) {
            int i = lane + kq * 32;
            if (i < 240) *(float4*)&buf[i >> 3][(i & 7) * 4] = pre[kq];
        }
        __syncwarp();
        if (t < 3) {
#pragma unroll
            for (int kq = 0; kq < 8; kq++) {
                int i = lane + kq * 32;
                if (i < 240) pre[kq] = xw4[(i >> 3) * 32 + (t + 1) * 8 + (i & 7)];
            }
        }
        if (lane < WCH) {
            float4* my = (float4*)buf[lane];
#pragma unroll
            for (int q = 0; q < 8; q++) {
                float4 v = my[q];
                float4 ov;
                ov.x = step_all(v.x, zst, kc);
                ov.y = step_all(v.y, zst, kc);
                ov.z = step_all(v.z, zst, kc);
                ov.w = step_all(v.w, zst, kc);
                my[q] = ov;
            }
        }
        __syncwarp();
#pragma unroll
        for (int kq = 0; kq < 8; kq++) {
            int i = lane + kq * 32;
            if (i < 240)
                yw4[(i >> 3) * 32 + t * 8 + (i & 7)] = *(const float4*)&buf[i >> 3][(i & 7) * 4];
        }
        __syncwarp();
    }
}

// ----------------------------------------------------------------- launch --

extern "C" void kernel_launch(void* const* d_in, const int* in_sizes, int n_in,
                              void* d_out, int out_size) {
    const float* x   = (const float*)d_in[0];
    const float* lg  = (const float*)d_in[1];
    const float* mg  = (const float*)d_in[2];
    const float* mfc = (const float*)d_in[3];
    const float* mq  = (const float*)d_in[4];
    const float* hg  = (const float*)d_in[5];
    float* y = (float*)d_out;

    setup_kernel<<<1, 256>>>(lg, mg, mfc, mq, hg);
    fused_kernel<<<GRID, THREADS>>>(x, y);
}